// round 17
// baseline (speedup 1.0000x reference)
#include <cuda_runtime.h>
#include <cuda_bf16.h>
#include <cuda_fp16.h>
#include <cstdint>

#define BB 256
#define TT 20
#define HH 512
#define WVV 301
#define FF 196
#define CC 512
#define VV 9871
#define XK 813
#define NAG 708

#define KSEC 832          // padded K section (>=813, mult of 32)
#define LKP 1664          // 2 * KSEC (fp16 hi|lo)
#define NSEC 26           // 832 / 32 iters per section

#define KP2 512           // vocab K (single fp16 term)
#define NPAD 9984
#define MROWS (TT * BB)   // 5120

// ---------------- device globals ------------------------------------------------
__device__ __half g_Aattn[(size_t)TT * BB * LKP];  // [x|h] hi|lo
__device__ __half g_Acomb[(size_t)TT * BB * LKP];  // [x|ctx] hi|lo
__device__ __half g_Aih[(size_t)BB * LKP];         // [inp|h] hi|lo
__device__ __half g_Wag2[(size_t)768 * LKP];       // [Whi|Wlo]
__device__ __half g_Wcomb2[(size_t)320 * LKP];
__device__ __half g_Wl2i[(size_t)2048 * LKP];      // gate-interleaved rows n'=4j+gate
__device__ __half g_enc2[(size_t)BB * CC * FF];    // fp16 encoding copy
__device__ float g_ag_s[2 * BB * 768];     // attn+gate logit slices (split-2)
__device__ float g_cst[BB * HH];           // cell state
__device__ float g_bli[2048];              // interleaved bih+bhh (4j+gate)
__device__ __half g_ap2[(size_t)MROWS * KP2];  // vocab A (fp16 h)
__device__ __half g_wp2[(size_t)NPAD * KP2];   // vocab W (fp16)

// ---------------- common helpers ------------------------------------------------
__device__ __forceinline__ uint32_t smem_u32(const void* p) {
    uint32_t a;
    asm("{ .reg .u64 t; cvta.to.shared.u64 t, %1; cvt.u32.u64 %0, t; }" : "=r"(a) : "l"(p));
    return a;
}
__device__ __forceinline__ void cp16(uint32_t saddr, const void* gptr) {
    asm volatile("cp.async.cg.shared.global [%0], [%1], 16;" :: "r"(saddr), "l"(gptr));
}
__device__ __forceinline__ void cp_commit() { asm volatile("cp.async.commit_group;"); }
template <int N>
__device__ __forceinline__ void cp_wait() { asm volatile("cp.async.wait_group %0;" :: "n"(N)); }
__device__ __forceinline__ void ldm_x4(uint32_t* r, uint32_t addr) {
    asm volatile("ldmatrix.sync.aligned.m8n8.x4.shared.b16 {%0,%1,%2,%3}, [%4];"
                 : "=r"(r[0]), "=r"(r[1]), "=r"(r[2]), "=r"(r[3]) : "r"(addr));
}
__device__ __forceinline__ void mma_fp16(float* c, const uint32_t* a, uint32_t b0, uint32_t b1) {
    asm volatile(
        "mma.sync.aligned.m16n8k16.row.col.f32.f16.f16.f32 "
        "{%0,%1,%2,%3}, {%4,%5,%6,%7}, {%8,%9}, {%0,%1,%2,%3};"
        : "+f"(c[0]), "+f"(c[1]), "+f"(c[2]), "+f"(c[3])
        : "r"(a[0]), "r"(a[1]), "r"(a[2]), "r"(a[3]), "r"(b0), "r"(b1));
}
__device__ __forceinline__ uint32_t swz(int row, int c) {
    return (uint32_t)(row * 64 + ((c ^ ((row >> 1) & 3)) * 16));
}
__device__ __forceinline__ void split_fp16(float v, __half& hi, __half& lo) {
    hi = __float2half(v);
    lo = __float2half(v - __half2float(hi));
}

// ---- 64x64 tile fp16 GEMM, 6-stage pipeline, single sync per iteration --------
template <int NIT>
__device__ __forceinline__ void tile_mma(const __half* __restrict__ Ag,
                                         const __half* __restrict__ Bg,
                                         int bm, int bn, int koff, char* spipe,
                                         float acc[4][4]) {
    uint32_t smb = smem_u32(spipe);
    int tid = threadIdx.x;
    int wid = tid >> 5, lane = tid & 31;
    int wm = wid & 3, wn = wid >> 2;
    int a_r = lane & 15, a_c = lane >> 4;
    int b_r = (lane & 7) | (((lane >> 4) & 1) << 3);
    int b_c = (lane >> 3) & 1;
    int lrow = tid >> 2, lc = tid & 3;
#pragma unroll
    for (int q = 0; q < 4; q++)
#pragma unroll
        for (int j = 0; j < 4; j++) acc[q][j] = 0.f;

    const __half* Abase = Ag + (size_t)(bm + lrow) * LKP + koff + lc * 8;
    const __half* Bbase = Bg + (size_t)(bn + lrow) * LKP + koff + lc * 8;

#pragma unroll
    for (int st = 0; st < 5; st++) {
        if (st < NIT) {
            uint32_t ab = smb + st * 8192;
            cp16(ab + swz(lrow, lc), Abase + st * 32);
            cp16(ab + 4096 + swz(lrow, lc), Bbase + st * 32);
        }
        cp_commit();
    }
    for (int kt = 0; kt < NIT; kt++) {
        cp_wait<4>();
        __syncthreads();
        int nx = kt + 5;
        if (nx < NIT) {
            uint32_t ab = smb + (nx % 6) * 8192;
            cp16(ab + swz(lrow, lc), Abase + (size_t)nx * 32);
            cp16(ab + 4096 + swz(lrow, lc), Bbase + (size_t)nx * 32);
        }
        cp_commit();
        uint32_t ab = smb + (kt % 6) * 8192;
        uint32_t bb = ab + 4096;
#pragma unroll
        for (int s = 0; s < 2; s++) {
            uint32_t af[4];
            ldm_x4(af, ab + swz(wm * 16 + a_r, s * 2 + a_c));
#pragma unroll
            for (int jj = 0; jj < 2; jj++) {
                uint32_t bf[4];
                ldm_x4(bf, bb + swz(wn * 32 + jj * 16 + b_r, s * 2 + b_c));
                mma_fp16(acc[2 * jj], af, bf[0], bf[1]);
                mma_fp16(acc[2 * jj + 1], af, bf[2], bf[3]);
            }
        }
    }
}

// ---- WIDE 64x128 tile fp16 GEMM, 5-stage (12KB/stage), single sync ------------
#define WSTG 12288
#define WSMEM (5 * WSTG)
template <int NIT>
__device__ __forceinline__ void tile_mma_w(const __half* __restrict__ Ag,
                                           const __half* __restrict__ Bg,
                                           int bm, int bn, int koff, char* spipe,
                                           float acc[8][4]) {
    uint32_t smb = smem_u32(spipe);
    int tid = threadIdx.x;
    int wid = tid >> 5, lane = tid & 31;
    int wm = wid & 3, wn = wid >> 2;
    int a_r = lane & 15, a_c = lane >> 4;
    int b_r = (lane & 7) | (((lane >> 4) & 1) << 3);
    int b_c = (lane >> 3) & 1;
#pragma unroll
    for (int q = 0; q < 8; q++)
#pragma unroll
        for (int j = 0; j < 4; j++) acc[q][j] = 0.f;

    int arow = tid >> 2, ac = tid & 3;
    const __half* Abase = Ag + (size_t)(bm + arow) * LKP + koff + ac * 8;
    const __half* B0 = Bg + (size_t)(bn + arow) * LKP + koff + ac * 8;
    const __half* B1 = Bg + (size_t)(bn + 64 + arow) * LKP + koff + ac * 8;
    uint32_t aoff = swz(arow, ac);
    uint32_t boff0 = 4096 + swz(arow, ac);
    uint32_t boff1 = 4096 + swz(64 + arow, ac);

#pragma unroll
    for (int st = 0; st < 4; st++) {
        if (st < NIT) {
            uint32_t base = smb + st * WSTG;
            cp16(base + aoff, Abase + st * 32);
            cp16(base + boff0, B0 + st * 32);
            cp16(base + boff1, B1 + st * 32);
        }
        cp_commit();
    }
    for (int kt = 0; kt < NIT; kt++) {
        cp_wait<3>();
        __syncthreads();
        int nx = kt + 4;
        if (nx < NIT) {
            uint32_t base = smb + (nx % 5) * WSTG;
            cp16(base + aoff, Abase + (size_t)nx * 32);
            cp16(base + boff0, B0 + (size_t)nx * 32);
            cp16(base + boff1, B1 + (size_t)nx * 32);
        }
        cp_commit();
        uint32_t ab = smb + (kt % 5) * WSTG;
        uint32_t bb = ab + 4096;
#pragma unroll
        for (int s = 0; s < 2; s++) {
            uint32_t af[4];
            ldm_x4(af, ab + swz(wm * 16 + a_r, s * 2 + a_c));
#pragma unroll
            for (int jj = 0; jj < 4; jj++) {
                uint32_t bf[4];
                ldm_x4(bf, bb + swz(wn * 64 + jj * 16 + b_r, s * 2 + b_c));
                mma_fp16(acc[2 * jj], af, bf[0], bf[1]);
                mma_fp16(acc[2 * jj + 1], af, bf[2], bf[3]);
            }
        }
    }
}

// ---------------- setup kernels (4 launches before loop) ------------------------
__global__ void zero_all_kernel() {
    size_t stride = (size_t)gridDim.x * blockDim.x;
    size_t id = (size_t)blockIdx.x * blockDim.x + threadIdx.x;
    uint4 z = make_uint4(0, 0, 0, 0);
    uint4* pa = (uint4*)g_Aattn;
    size_t nA = sizeof(g_Aattn) / 16;
    for (size_t i = id; i < nA; i += stride) pa[i] = z;
    uint4* pc = (uint4*)g_Acomb;
    for (size_t i = id; i < nA; i += stride) pc[i] = z;
    uint4* pi = (uint4*)g_Aih;
    size_t nI = sizeof(g_Aih) / 16;
    for (size_t i = id; i < nI; i += stride) pi[i] = z;
    uint4* ps = (uint4*)g_cst;
    size_t nS = sizeof(g_cst) / 16;
    for (size_t i = id; i < nS; i += stride) ps[i] = z;
}

__global__ void setup_enc_kernel(const float* __restrict__ enc) {
    size_t stride = (size_t)gridDim.x * blockDim.x;
    size_t total = (size_t)BB * CC * FF;
    for (size_t i = (size_t)blockIdx.x * blockDim.x + threadIdx.x; i < total; i += stride)
        g_enc2[i] = __float2half(enc[i]);
}

__global__ void setup_x2_kernel(const float* __restrict__ wv) {
    int idx = blockIdx.x * blockDim.x + threadIdx.x;
    const int total = TT * BB * WVV;
    if (idx >= total) return;
    int t = idx / (BB * WVV);
    int r = idx % (BB * WVV);
    int b = r / WVV, w = r % WVV;
    float v = (t == 0) ? 0.f : wv[(size_t)b * TT * WVV + (size_t)(t - 1) * WVV + w];
    __half hi, lo;
    split_fp16(v, hi, lo);
    size_t base = ((size_t)t * BB + b) * LKP;
    g_Aattn[base + w] = hi;
    g_Aattn[base + KSEC + w] = lo;
    g_Acomb[base + w] = hi;
    g_Acomb[base + KSEC + w] = lo;
}

#define NW0 (768 * KSEC)
#define NW1 (320 * KSEC)
#define NW2 (2048 * KSEC)
#define NW3 (NPAD * HH)
__global__ void setup_weights_kernel(const float* __restrict__ attn_W,
                                     const float* __restrict__ gate_W,
                                     const float* __restrict__ comb_W,
                                     const float* __restrict__ Wih,
                                     const float* __restrict__ Whh,
                                     const float* __restrict__ bih,
                                     const float* __restrict__ bhh,
                                     const float* __restrict__ vw) {
    long idx = (long)blockIdx.x * blockDim.x + threadIdx.x;
    if (idx < 2048) {
        // interleaved bias: n' = 4j + gate  <-  orig gate*512 + j
        int j = (int)(idx >> 2), gate = (int)(idx & 3);
        int n = gate * 512 + j;
        g_bli[idx] = bih[n] + bhh[n];
    }
    __half hi, lo;
    if (idx < NW0) {
        int n = idx / KSEC, k = idx % KSEC;
        float v = 0.f;
        if (k < XK) {
            if (n < FF) v = attn_W[(size_t)n * XK + k];
            else if (n < NAG && k >= WVV) v = gate_W[(size_t)(n - FF) * HH + (k - WVV)];
        }
        split_fp16(v, hi, lo);
        size_t base = (size_t)n * LKP;
        g_Wag2[base + k] = hi;
        g_Wag2[base + KSEC + k] = lo;
        return;
    }
    idx -= NW0;
    if (idx < NW1) {
        int n = idx / KSEC, k = idx % KSEC;
        float v = (n < WVV && k < XK) ? comb_W[(size_t)n * XK + k] : 0.f;
        split_fp16(v, hi, lo);
        size_t base = (size_t)n * LKP;
        g_Wcomb2[base + k] = hi;
        g_Wcomb2[base + KSEC + k] = lo;
        return;
    }
    idx -= NW1;
    if (idx < NW2) {
        int np = idx / KSEC, k = idx % KSEC;   // np = interleaved row 4j+gate
        int j = np >> 2, gate = np & 3;
        int n = gate * 512 + j;                // original row
        float v = 0.f;
        if (k < XK) v = (k < WVV) ? Wih[(size_t)n * WVV + k] : Whh[(size_t)n * HH + (k - WVV)];
        split_fp16(v, hi, lo);
        size_t base = (size_t)np * LKP;
        g_Wl2i[base + k] = hi;
        g_Wl2i[base + KSEC + k] = lo;
        return;
    }
    idx -= NW2;
    if (idx < NW3) {
        int n = idx / HH, k = idx % HH;
        float v = (n < VV) ? vw[(size_t)n * HH + k] : 0.f;
        g_wp2[(size_t)n * KP2 + k] = __float2half(v);
    }
}

// ---------------- loop kernels (4 per step) --------------------------------------
// P1: attn+gate logits, WIDE tiles, split-2. grid = 48
__global__ void __launch_bounds__(256) k_p1(const __half* __restrict__ A) {
    extern __shared__ __align__(16) char s_dyn[];
    float acc[8][4];
    int job = blockIdx.x;
    int z = job & 1, tile = job >> 1;
    int bm = (tile / 6) * 64, bn = (tile % 6) * 128;
    tile_mma_w<NSEC>(A, g_Wag2, bm, bn, z * KSEC, s_dyn, acc);
    int tid = threadIdx.x, wid = tid >> 5, lane = tid & 31;
    float* dst = g_ag_s + (size_t)z * BB * 768;
    int r0 = bm + (wid & 3) * 16 + (lane >> 2);
    int c0 = bn + (wid >> 2) * 64 + 2 * (lane & 3);
#pragma unroll
    for (int q = 0; q < 8; q++)
#pragma unroll
        for (int h = 0; h < 2; h++) {
            dst[(r0 + 8 * h) * 768 + c0 + q * 8] = acc[q][2 * h];
            dst[(r0 + 8 * h) * 768 + c0 + q * 8 + 1] = acc[q][2 * h + 1];
        }
}

// P2: softmax + gated ctx (sums 2 slices, fp16 encoding). grid = BB
__global__ void __launch_bounds__(256)
k_p2(const float* __restrict__ attn_b, const float* __restrict__ gate_b,
     __half* __restrict__ Acomb_t) {
    __shared__ float s_red[256];
    __shared__ __align__(16) float s_aw[196];
    int b = blockIdx.x;
    int tid = threadIdx.x;
    int wid = tid >> 5, lane = tid & 31;
    const float* p0 = g_ag_s + (size_t)b * 768;
    const float* p1 = p0 + (size_t)BB * 768;
    float v = -3.0e38f;
    if (tid < FF) v = attn_b[tid] + p0[tid] + p1[tid];
    s_red[tid] = v;
    __syncthreads();
    for (int s = 128; s > 0; s >>= 1) {
        if (tid < s) s_red[tid] = fmaxf(s_red[tid], s_red[tid + s]);
        __syncthreads();
    }
    float mx = s_red[0];
    __syncthreads();
    float e = (tid < FF) ? expf(v - mx) : 0.f;
    s_red[tid] = e;
    __syncthreads();
    for (int s = 128; s > 0; s >>= 1) {
        if (tid < s) s_red[tid] += s_red[tid + s];
        __syncthreads();
    }
    float inv = 1.f / s_red[0];
    __syncthreads();
    if (tid < FF) s_aw[tid] = e * inv;
    __syncthreads();
    const __half2* encb = (const __half2*)(g_enc2 + (size_t)b * CC * FF);
    size_t cbase = (size_t)b * LKP;
    for (int grp = 0; grp < 8; grp++) {
#pragma unroll
        for (int ci = 0; ci < 8; ci++) {
            int c = wid * 64 + grp * 8 + ci;
            const __half2* row = encb + (size_t)c * 98;
            float sum = 0.f;
#pragma unroll
            for (int it = 0; it < 4; it++) {
                int f = lane + it * 32;
                if (f < 98) {
                    float2 vf = __half22float2(row[f]);
                    sum += vf.x * s_aw[2 * f] + vf.y * s_aw[2 * f + 1];
                }
            }
#pragma unroll
            for (int o = 16; o > 0; o >>= 1) sum += __shfl_xor_sync(0xffffffffu, sum, o);
            if (lane == 0) {
                float gz = gate_b[c] + p0[FF + c] + p1[FF + c];
                float gamma = 1.f / (1.f + expf(-gz));
                float val = gamma * sum;
                __half hi, lo;
                split_fp16(val, hi, lo);
                Acomb_t[cbase + WVV + c] = hi;
                Acomb_t[cbase + KSEC + WVV + c] = lo;
            }
        }
    }
}

// P3: comb gemm FULL-K + fused bias/relu/split epilogue. grid = 20
__global__ void __launch_bounds__(256)
k_p3(const __half* __restrict__ A, const float* __restrict__ comb_b) {
    __shared__ __align__(16) char s_pipe[6 * 8192];
    float acc[4][4];
    int job = blockIdx.x;
    int bm = (job / 5) * 64, bn = (job % 5) * 64;
    tile_mma<2 * NSEC>(A, g_Wcomb2, bm, bn, 0, s_pipe, acc);
    int tid = threadIdx.x, wid = tid >> 5, lane = tid & 31;
    int r0 = bm + (wid & 3) * 16 + (lane >> 2);
    int c0 = bn + (wid >> 2) * 32 + 2 * (lane & 3);
#pragma unroll
    for (int q = 0; q < 4; q++)
#pragma unroll
        for (int h = 0; h < 2; h++) {
            int gm = r0 + 8 * h;
            size_t abase = (size_t)gm * LKP;
#pragma unroll
            for (int u = 0; u < 2; u++) {
                int n = c0 + q * 8 + u;
                if (n < WVV) {
                    float val = fmaxf(acc[q][2 * h + u] + comb_b[n], 0.f);
                    __half hi, lo;
                    split_fp16(val, hi, lo);
                    g_Aih[abase + n] = hi;
                    g_Aih[abase + KSEC + n] = lo;
                }
            }
        }
}

// P45: lstm gates gemm FULL-K (gate-interleaved W) + fused LSTM cell. grid = 64
__global__ void __launch_bounds__(256)
k_p45(int t, __half* __restrict__ Aattn_next) {
    extern __shared__ __align__(16) char s_dyn[];
    float acc[8][4];
    int job = blockIdx.x;
    int bm = (job / 16) * 64, bn = (job % 16) * 128;
    tile_mma_w<2 * NSEC>(g_Aih, g_Wl2i, bm, bn, 0, s_dyn, acc);
    int tid = threadIdx.x, wid = tid >> 5, lane = tid & 31;
    int r0 = bm + (wid & 3) * 16 + (lane >> 2);
    int c0 = bn + (wid >> 2) * 64 + 2 * (lane & 3);
    bool owner = ((lane & 1) == 0);   // even lane of pair computes the cell
#pragma unroll
    for (int q = 0; q < 8; q++) {
        int c = c0 + q * 8;           // first col of this thread's pair
#pragma unroll
        for (int h = 0; h < 2; h++) {
            int gm = r0 + 8 * h;      // batch index b
            float v0 = acc[q][2 * h] + g_bli[c];
            float v1 = acc[q][2 * h + 1] + g_bli[c + 1];
            float p0 = __shfl_xor_sync(0xffffffffu, v0, 1);
            float p1 = __shfl_xor_sync(0xffffffffu, v1, 1);
            if (owner) {
                // even lane: (v0,v1)=(i,f), partner (p0,p1)=(g,o)
                int j = c >> 2;
                int idx = gm * HH + j;
                float si = 1.f / (1.f + expf(-v0));
                float sf = 1.f / (1.f + expf(-v1));
                float so = 1.f / (1.f + expf(-p1));
                float cn = sf * g_cst[idx] + si * tanhf(p0);
                float hn = so * tanhf(cn);
                g_cst[idx] = cn;
                __half hi, lo;
                split_fp16(hn, hi, lo);
                size_t ib = (size_t)gm * LKP + WVV + j;
                g_Aih[ib] = hi;
                g_Aih[ib + KSEC] = lo;
                if (Aattn_next) {
                    Aattn_next[ib] = hi;
                    Aattn_next[ib + KSEC] = lo;
                }
                g_ap2[((size_t)t * BB + gm) * KP2 + j] = hi;
            }
        }
    }
}

// ===================== vocab GEMM (fp16, one launch at end) =====================
#define VBM 128
#define VBN 256
#define NKT2 (KP2 / 32)    // 16
#define STAGE_BYTES 24576
#define ASZ 8192
#define NSTAGE 3
#define VSMEM (NSTAGE * STAGE_BYTES)

__device__ __forceinline__ void issue_tile(const __half* __restrict__ Ag,
                                           const __half* __restrict__ Bg,
                                           uint32_t smb, int stage, int bm, int bn, int kt) {
    int tid = threadIdx.x;
    uint32_t abase = smb + stage * STAGE_BYTES;
    uint32_t bbase = abase + ASZ;
#pragma unroll
    for (int l = 0; l < 2; l++) {
        int idx = tid + 256 * l;
        int row = idx >> 2, c = idx & 3;
        cp16(abase + swz(row, c), Ag + (size_t)(bm + row) * KP2 + kt * 32 + c * 8);
    }
#pragma unroll
    for (int l = 0; l < 4; l++) {
        int idx = tid + 256 * l;
        int row = idx >> 2, c = idx & 3;
        cp16(bbase + swz(row, c), Bg + (size_t)(bn + row) * KP2 + kt * 32 + c * 8);
    }
    cp_commit();
}

__global__ void __launch_bounds__(256, 1)
gemm_vocab_mma(const __half* __restrict__ Ag, const __half* __restrict__ Bg,
               const float* __restrict__ bias, float* __restrict__ out) {
    extern __shared__ char sm[];
    uint32_t smb = smem_u32(sm);
    int tid = threadIdx.x;
    int wid = tid >> 5, lane = tid & 31;
    int wm = wid & 1, wn = wid >> 1;
    int bm = blockIdx.y * VBM, bn = blockIdx.x * VBN;

    int a_r = lane & 15;
    int a_c = lane >> 4;
    int b_r = (lane & 7) | (((lane >> 4) & 1) << 3);
    int b_c = (lane >> 3) & 1;

    float acc[4][8][4];
#pragma unroll
    for (int i = 0; i < 4; i++)
#pragma unroll
        for (int j = 0; j < 8; j++)
#pragma unroll
            for (int q = 0; q < 4; q++) acc[i][j][q] = 0.f;

    issue_tile(Ag, Bg, smb, 0, bm, bn, 0);
    issue_tile(Ag, Bg, smb, 1, bm, bn, 1);

    for (int kt = 0; kt < NKT2; kt++) {
        cp_wait<1>();
        __syncthreads();
        if (kt + 2 < NKT2) issue_tile(Ag, Bg, smb, (kt + 2) % NSTAGE, bm, bn, kt + 2);
        uint32_t abase = smb + (kt % NSTAGE) * STAGE_BYTES;
        uint32_t bbase = abase + ASZ;
#pragma unroll
        for (int s = 0; s < 2; s++) {
            uint32_t af[4][4], bf[4][4];
#pragma unroll
            for (int i = 0; i < 4; i++) {
                int row = wm * 64 + i * 16 + a_r;
                ldm_x4(af[i], abase + swz(row, s * 2 + a_c));
            }
#pragma unroll
            for (int jj = 0; jj < 4; jj++) {
                int row = wn * 64 + jj * 16 + b_r;
                ldm_x4(bf[jj], bbase + swz(row, s * 2 + b_c));
            }
#pragma unroll
            for (int i = 0; i < 4; i++)
#pragma unroll
                for (int jj = 0; jj < 4; jj++) {
                    mma_fp16(acc[i][2 * jj], af[i], bf[jj][0], bf[jj][1]);
                    mma_fp16(acc[i][2 * jj + 1], af[i], bf[jj][2], bf[jj][3]);
                }
        }
    }

#pragma unroll
    for (int i = 0; i < 4; i++) {
#pragma unroll
        for (int j = 0; j < 8; j++) {
            int gm0 = bm + wm * 64 + i * 16 + (lane >> 2);
            int gn = bn + wn * 64 + j * 8 + 2 * (lane & 3);
#pragma unroll
            for (int h = 0; h < 2; h++) {
                int gm = gm0 + h * 8;
                int t = gm >> 8, b = gm & 255;
                float* row = out + ((size_t)b * TT + t) * VV;
                float c0 = acc[i][j][2 * h], c1 = acc[i][j][2 * h + 1];
                if (gn < VV) row[gn] = c0 + bias[gn];
                if (gn + 1 < VV) row[gn + 1] = c1 + bias[gn + 1];
            }
        }
    }
}

// ---------------- host launch (single stream, zero events) ----------------------
extern "C" void kernel_launch(void* const* d_in, const int* in_sizes, int n_in,
                              void* d_out, int out_size) {
    const float* enc     = (const float*)d_in[0];
    const float* wv      = (const float*)d_in[1];
    const float* attn_W  = (const float*)d_in[2];
    const float* attn_b  = (const float*)d_in[3];
    const float* comb_W  = (const float*)d_in[4];
    const float* comb_b  = (const float*)d_in[5];
    const float* gate_W  = (const float*)d_in[6];
    const float* gate_b  = (const float*)d_in[7];
    const float* Wih     = (const float*)d_in[8];
    const float* Whh     = (const float*)d_in[9];
    const float* bih     = (const float*)d_in[10];
    const float* bhh     = (const float*)d_in[11];
    const float* vocab_W = (const float*)d_in[12];
    const float* vocab_b = (const float*)d_in[13];
    float* out = (float*)d_out;

    __half *p_Aattn, *p_Acomb, *p_ap2, *p_wp2;
    cudaGetSymbolAddress((void**)&p_Aattn, g_Aattn);
    cudaGetSymbolAddress((void**)&p_Acomb, g_Acomb);
    cudaGetSymbolAddress((void**)&p_ap2, g_ap2);
    cudaGetSymbolAddress((void**)&p_wp2, g_wp2);

    cudaFuncSetAttribute(gemm_vocab_mma, cudaFuncAttributeMaxDynamicSharedMemorySize, VSMEM);
    cudaFuncSetAttribute(k_p1, cudaFuncAttributeMaxDynamicSharedMemorySize, WSMEM);
    cudaFuncSetAttribute(k_p45, cudaFuncAttributeMaxDynamicSharedMemorySize, WSMEM);

    zero_all_kernel<<<1024, 256>>>();
    setup_enc_kernel<<<2048, 256>>>(enc);
    setup_x2_kernel<<<(TT * BB * WVV + 255) / 256, 256>>>(wv);
    {
        long total = (long)NW0 + NW1 + NW2 + NW3;
        setup_weights_kernel<<<(unsigned)((total + 255) / 256), 256>>>(
            attn_W, gate_W, comb_W, Wih, Whh, bih, bhh, vocab_W);
    }

    for (int t = 0; t < TT; t++) {
        const __half* Aat = p_Aattn + (size_t)t * BB * LKP;
        __half* Aco = p_Acomb + (size_t)t * BB * LKP;
        k_p1<<<48, 256, WSMEM>>>(Aat);
        k_p2<<<BB, 256>>>(attn_b, gate_b, Aco);
        k_p3<<<20, 256>>>(Aco, comb_b);
        __half* Anext = (t + 1 < TT) ? (p_Aattn + (size_t)(t + 1) * BB * LKP) : (__half*)nullptr;
        k_p45<<<64, 256, WSMEM>>>(t, Anext);
    }
    gemm_vocab_mma<<<dim3(NPAD / VBN, MROWS / VBM), 256, VSMEM>>>(p_ap2, p_wp2, vocab_b, out);
}